// round 2
// baseline (speedup 1.0000x reference)
#include <cuda_runtime.h>
#include <math.h>

#define BB 32
#define LL 128
#define WW 16
#define CEMB 64
#define NF 128
#define WEMB 256
#define EMB 384
#define HH 512
#define GG 2048
#define NT 4096
#define NCLS 17

#define CNN_SMEM ((128*193 + 8*16*64) * 4)

// ---------------- scratch (device globals: no allocation allowed) ----------
__device__ float g_X[NT * EMB];                       // [token=l*32+b][384]
__device__ float g_gx[(size_t)2 * LL * GG * BB];      // [dir][t][gate][b]
__device__ float g_hbuf[2 * 2 * HH * BB];             // ping-pong [buf][dir][c][b]
__device__ float g_hall[(size_t)NT * 1024];           // [token][1024]
__device__ float g_z[(size_t)NT * 512];               // [token][512]
__device__ unsigned g_count;
__device__ unsigned g_gen;

// ---------------- DIY grid barrier (all 128 blocks resident) ---------------
__device__ __forceinline__ void grid_sync(unsigned nb) {
    __threadfence();
    __syncthreads();
    if (threadIdx.x == 0) {
        volatile unsigned* vg = &g_gen;
        unsigned gen = *vg;
        unsigned arr = atomicAdd(&g_count, 1u);
        if (arr == nb - 1u) {
            atomicExch(&g_count, 0u);
            __threadfence();
            atomicExch((unsigned*)&g_gen, gen + 1u);
        } else {
            while (*vg == gen) { __nanosleep(64); }
        }
    }
    __syncthreads();
}

// ---------------- init: zero h ping buffer + barrier state -----------------
__global__ void init_kernel() {
    int i = blockIdx.x * blockDim.x + threadIdx.x;
    if (i == 0) { g_count = 0u; g_gen = 0u; }
    for (int j = i; j < 2 * HH * BB; j += gridDim.x * blockDim.x)
        g_hbuf[j] = 0.0f;   // buffer 0 (read by step 0)
}

// ---------------- word embedding gather -> X[:,128:384] --------------------
__global__ void embed_kernel(const int* __restrict__ wid,
                             const float* __restrict__ wemb) {
    int idx = blockIdx.x * blockDim.x + threadIdx.x;   // 4096*64
    int token = idx >> 6;
    int j = idx & 63;
    int l = token >> 5;
    int b = token & 31;
    int w = wid[b * LL + l];
    float4 v = *(const float4*)(wemb + (size_t)w * WEMB + j * 4);
    *(float4*)(g_X + (size_t)token * EMB + NF + j * 4) = v;
}

// ---------------- char CNN + relu + maxpool -> X[:,0:128] ------------------
__global__ void __launch_bounds__(256) cnn_kernel(const int* __restrict__ cid,
                                                  const float* __restrict__ cemb,
                                                  const float* __restrict__ cw,
                                                  const float* __restrict__ cb) {
    extern __shared__ float sm[];
    float* ws = sm;                 // [128][193] padded conv weights
    float* ce = sm + 128 * 193;     // [8][16][64] char embeddings
    int tid = threadIdx.x;

    for (int i = tid; i < NF * 192; i += 256)
        ws[(i / 192) * 193 + (i % 192)] = cw[i];

    int p0 = blockIdx.x * 8;        // p = b*128 + l
    for (int i = tid; i < 8 * WW * CEMB; i += 256) {
        int q = i >> 10;
        int w = (i >> 6) & 15;
        int c = i & 63;
        int id = cid[(p0 + q) * WW + w];
        ce[i] = cemb[id * CEMB + c];
    }
    __syncthreads();

    int f  = tid & 127;
    int qh = tid >> 7;              // 0/1 -> positions 0..3 / 4..7
    float bias = cb[f];
    const float* wsf = ws + f * 193;

    for (int qq = 0; qq < 4; qq++) {
        int q = qh * 4 + qq;
        float acc[WW];
#pragma unroll
        for (int w = 0; w < WW; w++) acc[w] = bias;
        const float* cep = ce + q * (WW * CEMB);
        for (int c = 0; c < CEMB; c++) {
            float cr[WW];
#pragma unroll
            for (int w = 0; w < WW; w++) cr[w] = cep[w * CEMB + c];
            float k0 = wsf[c * 3 + 0];
            float k1 = wsf[c * 3 + 1];
            float k2 = wsf[c * 3 + 2];
#pragma unroll
            for (int w = 1; w < WW; w++)     acc[w] = fmaf(cr[w - 1], k0, acc[w]);
#pragma unroll
            for (int w = 0; w < WW; w++)     acc[w] = fmaf(cr[w],     k1, acc[w]);
#pragma unroll
            for (int w = 0; w < WW - 1; w++) acc[w] = fmaf(cr[w + 1], k2, acc[w]);
        }
        float m = 0.0f;
#pragma unroll
        for (int w = 0; w < WW; w++) m = fmaxf(m, acc[w]);
        int p = p0 + q;
        int bq = p >> 7;
        int lq = p & 127;
        g_X[(size_t)(lq * BB + bq) * EMB + f] = m;
    }
}

// ---------------- 128x128x8 register-tiled SGEMM (NT layout: C=A*B^T+bias) -
// MODE 0: write to gx layout [t][g][b] (+bias)
// MODE 1: elu(C+bias), row-major [M][N]
template <int MODE>
__global__ void __launch_bounds__(256) sgemm_kernel(const float* __restrict__ A,
                                                    const float* __restrict__ Bw,
                                                    const float* __restrict__ bias,
                                                    float* __restrict__ C,
                                                    int M, int N, int K) {
    __shared__ float As[8][128];
    __shared__ float Bs[8][128];
    int tid = threadIdx.x;
    int bm = blockIdx.y * 128;
    int bn = blockIdx.x * 128;
    int lrow = tid >> 1;
    int lcol = (tid & 1) * 4;
    const float* Ag = A + (size_t)(bm + lrow) * K + lcol;
    const float* Bg = Bw + (size_t)(bn + lrow) * K + lcol;
    int ty = tid >> 4, tx = tid & 15;

    float acc[8][8];
#pragma unroll
    for (int i = 0; i < 8; i++)
#pragma unroll
        for (int j = 0; j < 8; j++) acc[i][j] = 0.0f;

    for (int k0 = 0; k0 < K; k0 += 8) {
        float4 a4 = *(const float4*)(Ag + k0);
        float4 b4 = *(const float4*)(Bg + k0);
        As[lcol + 0][lrow] = a4.x; As[lcol + 1][lrow] = a4.y;
        As[lcol + 2][lrow] = a4.z; As[lcol + 3][lrow] = a4.w;
        Bs[lcol + 0][lrow] = b4.x; Bs[lcol + 1][lrow] = b4.y;
        Bs[lcol + 2][lrow] = b4.z; Bs[lcol + 3][lrow] = b4.w;
        __syncthreads();
#pragma unroll
        for (int k = 0; k < 8; k++) {
            float ar[8], br[8];
            *(float4*)(ar)     = *(const float4*)&As[k][ty * 8];
            *(float4*)(ar + 4) = *(const float4*)&As[k][ty * 8 + 4];
            *(float4*)(br)     = *(const float4*)&Bs[k][tx * 8];
            *(float4*)(br + 4) = *(const float4*)&Bs[k][tx * 8 + 4];
#pragma unroll
            for (int i = 0; i < 8; i++)
#pragma unroll
                for (int j = 0; j < 8; j++)
                    acc[i][j] = fmaf(ar[i], br[j], acc[i][j]);
        }
        __syncthreads();
    }

#pragma unroll
    for (int i = 0; i < 8; i++) {
        int m = bm + ty * 8 + i;
#pragma unroll
        for (int j = 0; j < 8; j++) {
            int n = bn + tx * 8 + j;
            float v = acc[i][j] + bias[n];
            if (MODE == 0) {
                int t = m >> 5, bb2 = m & 31;
                C[((size_t)t * GG + n) * BB + bb2] = v;
            } else {
                if (v < 0.0f) v = expm1f(v);
                C[(size_t)m * N + n] = v;
            }
        }
    }
}

// ---------------- persistent BiLSTM: 128 blocks, 1 grid barrier per step ---
__global__ void __launch_bounds__(256) lstm_kernel(const float* __restrict__ whh_f,
                                                   const float* __restrict__ whh_b) {
    extern __shared__ float hs[];   // [512][32] h transposed, this dir
    int tid = threadIdx.x;
    int dir = blockIdx.x >> 6;
    int chunk = blockIdx.x & 63;
    int j0 = chunk * 8;
    const float* whh = dir ? whh_b : whh_f;
    int b = tid & 31;
    int cg = tid >> 5;
    int j = j0 + cg;
    const float* wri = whh + (size_t)(0 * HH + j) * HH;
    const float* wrf = whh + (size_t)(1 * HH + j) * HH;
    const float* wrg = whh + (size_t)(2 * HH + j) * HH;
    const float* wro = whh + (size_t)(3 * HH + j) * HH;

    float cstate = 0.0f;

    for (int step = 0; step < LL; step++) {
        int t = dir ? (LL - 1 - step) : step;
        const float* hread = g_hbuf + (size_t)(step & 1) * (2 * HH * BB) + dir * (HH * BB);
        float* hwrite = g_hbuf + (size_t)((step & 1) ^ 1) * (2 * HH * BB) + dir * (HH * BB);

        // stage h (this dir) into smem
        const float4* src = (const float4*)hread;
        float4* dst = (float4*)hs;
        for (int i = tid; i < (HH * BB) / 4; i += 256) dst[i] = src[i];
        __syncthreads();

        const float* gxp = g_gx + ((size_t)dir * LL + t) * (size_t)(GG * BB);
        float ai = gxp[(size_t)(0 * HH + j) * BB + b];
        float af = gxp[(size_t)(1 * HH + j) * BB + b];
        float ag = gxp[(size_t)(2 * HH + j) * BB + b];
        float ao = gxp[(size_t)(3 * HH + j) * BB + b];

#pragma unroll 2
        for (int c = 0; c < HH; c += 4) {
            float4 vi = *(const float4*)(wri + c);
            float4 vf = *(const float4*)(wrf + c);
            float4 vg = *(const float4*)(wrg + c);
            float4 vo = *(const float4*)(wro + c);
            float h0 = hs[(c + 0) * BB + b];
            float h1 = hs[(c + 1) * BB + b];
            float h2 = hs[(c + 2) * BB + b];
            float h3 = hs[(c + 3) * BB + b];
            ai = fmaf(vi.x, h0, ai); ai = fmaf(vi.y, h1, ai);
            ai = fmaf(vi.z, h2, ai); ai = fmaf(vi.w, h3, ai);
            af = fmaf(vf.x, h0, af); af = fmaf(vf.y, h1, af);
            af = fmaf(vf.z, h2, af); af = fmaf(vf.w, h3, af);
            ag = fmaf(vg.x, h0, ag); ag = fmaf(vg.y, h1, ag);
            ag = fmaf(vg.z, h2, ag); ag = fmaf(vg.w, h3, ag);
            ao = fmaf(vo.x, h0, ao); ao = fmaf(vo.y, h1, ao);
            ao = fmaf(vo.z, h2, ao); ao = fmaf(vo.w, h3, ao);
        }

        float si = 1.0f / (1.0f + __expf(-ai));
        float sf = 1.0f / (1.0f + __expf(-af));
        float so = 1.0f / (1.0f + __expf(-ao));
        float tg = tanhf(ag);
        cstate = fmaf(sf, cstate, si * tg);
        float hn = so * tanhf(cstate);

        hwrite[j * BB + b] = hn;
        g_hall[((size_t)t * BB + b) * 1024 + dir * HH + j] = hn;

        grid_sync(128);
    }
}

// ---------------- head 2: out = z @ w2^T + b2 ------------------------------
__global__ void __launch_bounds__(256) head2_kernel(const float* __restrict__ w2,
                                                    const float* __restrict__ b2,
                                                    float* __restrict__ out) {
    int warp = (blockIdx.x * blockDim.x + threadIdx.x) >> 5;
    int lane = threadIdx.x & 31;
    if (warp >= NT) return;
    const float* z = g_z + (size_t)warp * 512;
    float zr[16];
#pragma unroll
    for (int i = 0; i < 16; i++) zr[i] = z[lane + 32 * i];
    int l = warp >> 5, b = warp & 31;
    float* op = out + ((size_t)b * LL + l) * NCLS;
    for (int cls = 0; cls < NCLS; cls++) {
        const float* wr = w2 + cls * 512;
        float s = 0.0f;
#pragma unroll
        for (int i = 0; i < 16; i++) s = fmaf(zr[i], wr[lane + 32 * i], s);
#pragma unroll
        for (int o = 16; o > 0; o >>= 1) s += __shfl_xor_sync(0xffffffffu, s, o);
        if (lane == 0) op[cls] = s + b2[cls];
    }
}

// ---------------- launcher -------------------------------------------------
extern "C" void kernel_launch(void* const* d_in, const int* in_sizes, int n_in,
                              void* d_out, int out_size) {
    (void)in_sizes; (void)n_in; (void)out_size;
    const int*   word_ids = (const int*)d_in[0];
    const int*   char_ids = (const int*)d_in[1];
    // d_in[2] = mask (unused by reference)
    const float* char_emb = (const float*)d_in[3];
    const float* word_emb = (const float*)d_in[4];
    const float* conv_w   = (const float*)d_in[5];
    const float* conv_b   = (const float*)d_in[6];
    const float* w_ih_f   = (const float*)d_in[7];
    const float* w_hh_f   = (const float*)d_in[8];
    const float* b_f      = (const float*)d_in[9];
    const float* w_ih_b   = (const float*)d_in[10];
    const float* w_hh_b   = (const float*)d_in[11];
    const float* b_b      = (const float*)d_in[12];
    const float* w1       = (const float*)d_in[13];
    const float* b1       = (const float*)d_in[14];
    const float* w2       = (const float*)d_in[15];
    const float* b2       = (const float*)d_in[16];
    float* out = (float*)d_out;

    float *pX, *pGx, *pHall, *pZ;
    cudaGetSymbolAddress((void**)&pX,    g_X);
    cudaGetSymbolAddress((void**)&pGx,   g_gx);
    cudaGetSymbolAddress((void**)&pHall, g_hall);
    cudaGetSymbolAddress((void**)&pZ,    g_z);

    cudaFuncSetAttribute(cnn_kernel,  cudaFuncAttributeMaxDynamicSharedMemorySize, CNN_SMEM);
    cudaFuncSetAttribute(lstm_kernel, cudaFuncAttributeMaxDynamicSharedMemorySize, HH * BB * 4);

    init_kernel<<<64, 256>>>();
    embed_kernel<<<(NT * 64) / 256, 256>>>(word_ids, word_emb);
    cnn_kernel<<<512, 256, CNN_SMEM>>>(char_ids, char_emb, conv_w, conv_b);

    sgemm_kernel<0><<<dim3(GG / 128, NT / 128), 256>>>(pX, w_ih_f, b_f, pGx,
                                                       NT, GG, EMB);
    sgemm_kernel<0><<<dim3(GG / 128, NT / 128), 256>>>(pX, w_ih_b, b_b,
                                                       pGx + (size_t)LL * GG * BB,
                                                       NT, GG, EMB);

    lstm_kernel<<<128, 256, HH * BB * 4>>>(w_hh_f, w_hh_b);

    sgemm_kernel<1><<<dim3(512 / 128, NT / 128), 256>>>(pHall, w1, b1, pZ,
                                                        NT, 512, 1024);
    head2_kernel<<<(NT * 32) / 256, 256>>>(w2, b2, out);
}

// round 5
// speedup vs baseline: 1.2120x; 1.2120x over previous
#include <cuda_runtime.h>
#include <math.h>

typedef unsigned long long ull;

#define BB 32
#define LL 128
#define WW 16
#define CEMB 64
#define NF 128
#define WEMB 256
#define EMB 384
#define HH 512
#define GG 2048
#define NT 4096
#define NCLS 17

#define CNN_SMEM ((128*193 + 8*16*64) * 4)

// LSTM smem: dup-weights 8 cells * 4 gates * 512 ull + h 16 rows * 513 ull
#define WDUP_ULL (8 * 4 * 512)
#define HROW_PAD 513
#define HP_ULL (16 * HROW_PAD)
#define LSTM_SMEM ((WDUP_ULL + HP_ULL) * 8)

// ---------------- scratch (device globals: no allocation allowed) ----------
__device__ float g_X[NT * EMB];                       // [token=t*32+b][384]
__device__ float g_gx[(size_t)2 * LL * GG * BB];      // [dir][t][gate*512+cell][b]
__device__ ull   g_h2[2][2][16 * 512];                // ping-pong [buf][dir][b2*512+cell]
__device__ float g_hall2[(size_t)LL * 1024 * BB];     // [t][dir*512+cell][b]
__device__ float g_z[(size_t)NT * 512];               // [token][512]
__device__ unsigned g_count;
__device__ unsigned g_gen;

// ---------------- helpers --------------------------------------------------
__device__ __forceinline__ void ffma2(ull& d, ull a, ull b) {
    asm("fma.rn.f32x2 %0, %1, %2, %0;" : "+l"(d) : "l"(a), "l"(b));
}
__device__ __forceinline__ ull dup2(float v) {
    unsigned u = __float_as_uint(v);
    return ((ull)u << 32) | (ull)u;
}
__device__ __forceinline__ float lo2(ull x) { return __uint_as_float((unsigned)x); }
__device__ __forceinline__ float hi2(ull x) { return __uint_as_float((unsigned)(x >> 32)); }

// ---------------- DIY grid barrier (all 128 blocks resident) ---------------
__device__ __forceinline__ void grid_sync(unsigned nb) {
    __threadfence();
    __syncthreads();
    if (threadIdx.x == 0) {
        volatile unsigned* vg = &g_gen;
        unsigned gen = *vg;
        unsigned arr = atomicAdd(&g_count, 1u);
        if (arr == nb - 1u) {
            atomicExch(&g_count, 0u);
            __threadfence();
            atomicExch((unsigned*)&g_gen, gen + 1u);
        } else {
            while (*vg == gen) { __nanosleep(32); }
        }
    }
    __syncthreads();
}

// ---------------- init: zero h ping buffer + barrier state -----------------
__global__ void init_kernel() {
    int i = blockIdx.x * blockDim.x + threadIdx.x;
    if (i == 0) { g_count = 0u; g_gen = 0u; }
    if (i < 2 * 16 * 512) {
        g_h2[0][0][i] = 0ull;          // buffer 0, both dirs (i covers dir0+dir1 contiguously)
    }
}

// ---------------- word embedding gather -> X[:,128:384] --------------------
__global__ void embed_kernel(const int* __restrict__ wid,
                             const float* __restrict__ wemb) {
    int idx = blockIdx.x * blockDim.x + threadIdx.x;   // 4096*64
    int token = idx >> 6;
    int j = idx & 63;
    int l = token >> 5;
    int b = token & 31;
    int w = wid[b * LL + l];
    float4 v = *(const float4*)(wemb + (size_t)w * WEMB + j * 4);
    *(float4*)(g_X + (size_t)token * EMB + NF + j * 4) = v;
}

// ---------------- char CNN + relu + maxpool -> X[:,0:128] ------------------
__global__ void __launch_bounds__(256) cnn_kernel(const int* __restrict__ cid,
                                                  const float* __restrict__ cemb,
                                                  const float* __restrict__ cw,
                                                  const float* __restrict__ cb) {
    extern __shared__ float sm[];
    float* ws = sm;                 // [128][193] padded conv weights
    float* ce = sm + 128 * 193;     // [8][16][64] char embeddings
    int tid = threadIdx.x;

    for (int i = tid; i < NF * 192; i += 256)
        ws[(i / 192) * 193 + (i % 192)] = cw[i];

    int p0 = blockIdx.x * 8;        // p = b*128 + l
    for (int i = tid; i < 8 * WW * CEMB; i += 256) {
        int q = i >> 10;
        int w = (i >> 6) & 15;
        int c = i & 63;
        int id = cid[(p0 + q) * WW + w];
        ce[i] = cemb[id * CEMB + c];
    }
    __syncthreads();

    int f  = tid & 127;
    int qh = tid >> 7;
    float bias = cb[f];
    const float* wsf = ws + f * 193;

    for (int qq = 0; qq < 4; qq++) {
        int q = qh * 4 + qq;
        float acc[WW];
#pragma unroll
        for (int w = 0; w < WW; w++) acc[w] = bias;
        const float* cep = ce + q * (WW * CEMB);
        for (int c = 0; c < CEMB; c++) {
            float cr[WW];
#pragma unroll
            for (int w = 0; w < WW; w++) cr[w] = cep[w * CEMB + c];
            float k0 = wsf[c * 3 + 0];
            float k1 = wsf[c * 3 + 1];
            float k2 = wsf[c * 3 + 2];
#pragma unroll
            for (int w = 1; w < WW; w++)     acc[w] = fmaf(cr[w - 1], k0, acc[w]);
#pragma unroll
            for (int w = 0; w < WW; w++)     acc[w] = fmaf(cr[w],     k1, acc[w]);
#pragma unroll
            for (int w = 0; w < WW - 1; w++) acc[w] = fmaf(cr[w + 1], k2, acc[w]);
        }
        float m = 0.0f;
#pragma unroll
        for (int w = 0; w < WW; w++) m = fmaxf(m, acc[w]);
        int p = p0 + q;
        int bq = p >> 7;
        int lq = p & 127;
        g_X[(size_t)(lq * BB + bq) * EMB + f] = m;
    }
}

// ---------------- f32x2 128x128x8 register-tiled SGEMM ---------------------
// C = A * Bw^T + bias.  AMODE 0: A row-major [M][K].
//                       AMODE 1: A in [t][k][b] layout (m = t*32+b).
// OMODE 0: write [(m>>5)*N + n][b] "gx" layout.
// OMODE 1: elu, row-major [M][N].
template <int AMODE, int OMODE>
__global__ void __launch_bounds__(256, 2) sgemm2_kernel(const float* __restrict__ A,
                                                        const float* __restrict__ Bw,
                                                        const float* __restrict__ bias,
                                                        float* __restrict__ C,
                                                        int M, int N, int K) {
    __shared__ ull   Asd[8][130];   // dup-packed {a,a}
    __shared__ float Bs[8][128];
    int tid = threadIdx.x;
    int bm = blockIdx.y * 128;
    int bn = blockIdx.x * 128;
    int ty = tid >> 4, tx = tid & 15;

    // B loader indices (also A loader for AMODE 0)
    int lrow = tid >> 1;
    int lcol = (tid & 1) * 4;
    const float* Bg = Bw + (size_t)(bn + lrow) * K + lcol;

    ull acc[8][4];
#pragma unroll
    for (int i = 0; i < 8; i++)
#pragma unroll
        for (int q = 0; q < 4; q++) acc[i][q] = 0ull;

    for (int k0 = 0; k0 < K; k0 += 8) {
        // load B tile
        float4 b4 = *(const float4*)(Bg + k0);
        Bs[lcol + 0][lrow] = b4.x; Bs[lcol + 1][lrow] = b4.y;
        Bs[lcol + 2][lrow] = b4.z; Bs[lcol + 3][lrow] = b4.w;
        // load A tile (dup-packed)
        if (AMODE == 0) {
            const float* Ag = A + (size_t)(bm + lrow) * K + k0 + lcol;
            float4 a4 = *(const float4*)Ag;
            Asd[lcol + 0][lrow] = dup2(a4.x);
            Asd[lcol + 1][lrow] = dup2(a4.y);
            Asd[lcol + 2][lrow] = dup2(a4.z);
            Asd[lcol + 3][lrow] = dup2(a4.w);
        } else {
            int kk = tid >> 5;
            int mg = (tid & 31) * 4;
            int t  = (bm + mg) >> 5;
            int b0 = (bm + mg) & 31;
            float4 a4 = *(const float4*)(A + ((size_t)t * K + (k0 + kk)) * 32 + b0);
            Asd[kk][mg + 0] = dup2(a4.x);
            Asd[kk][mg + 1] = dup2(a4.y);
            Asd[kk][mg + 2] = dup2(a4.z);
            Asd[kk][mg + 3] = dup2(a4.w);
        }
        __syncthreads();
#pragma unroll
        for (int k = 0; k < 8; k++) {
            ull ar[8];
            ulonglong2 p0 = *(const ulonglong2*)&Asd[k][ty * 8 + 0];
            ulonglong2 p1 = *(const ulonglong2*)&Asd[k][ty * 8 + 2];
            ulonglong2 p2 = *(const ulonglong2*)&Asd[k][ty * 8 + 4];
            ulonglong2 p3 = *(const ulonglong2*)&Asd[k][ty * 8 + 6];
            ar[0] = p0.x; ar[1] = p0.y; ar[2] = p1.x; ar[3] = p1.y;
            ar[4] = p2.x; ar[5] = p2.y; ar[6] = p3.x; ar[7] = p3.y;
            ull br[4];
#pragma unroll
            for (int q = 0; q < 4; q++)
                br[q] = *(const ull*)&Bs[k][2 * (q * 16 + tx)];
#pragma unroll
            for (int i = 0; i < 8; i++)
#pragma unroll
                for (int q = 0; q < 4; q++)
                    ffma2(acc[i][q], ar[i], br[q]);
        }
        __syncthreads();
    }

#pragma unroll
    for (int i = 0; i < 8; i++) {
        int m = bm + ty * 8 + i;
#pragma unroll
        for (int q = 0; q < 4; q++) {
            int n0 = bn + 2 * (q * 16 + tx);
            float2 bv = *(const float2*)(bias + n0);
            float v0 = lo2(acc[i][q]) + bv.x;
            float v1 = hi2(acc[i][q]) + bv.y;
            if (OMODE == 0) {
                int t = m >> 5, b = m & 31;
                C[((size_t)t * N + n0) * 32 + b]       = v0;
                C[((size_t)t * N + n0 + 1) * 32 + b]   = v1;
            } else {
                if (v0 < 0.0f) v0 = expm1f(v0);
                if (v1 < 0.0f) v1 = expm1f(v1);
                *(float2*)(C + (size_t)m * N + n0) = make_float2(v0, v1);
            }
        }
    }
}

// ---------------- persistent BiLSTM ----------------------------------------
// 128 blocks (64/dir * 8 cells), thread = (cell, gate-pair, b-pair).
__global__ void __launch_bounds__(256) lstm_kernel(const float* __restrict__ whh_f,
                                                   const float* __restrict__ whh_b) {
    extern __shared__ ull smu[];
    ull* wdup = smu;                // [cell*4+gate][512] dup f32x2
    ull* hp   = smu + WDUP_ULL;     // [b2][513]

    int tid = threadIdx.x;
    int dir = blockIdx.x >> 6;
    int chunk = blockIdx.x & 63;
    int j0 = chunk * 8;
    const float* whh = dir ? whh_b : whh_f;

    int cell  = tid >> 5;
    int gpair = (tid >> 4) & 1;
    int b2    = tid & 15;
    int jglob = j0 + cell;
    int g0 = 2 * gpair, g1 = g0 + 1;

    // preload weights (once): dup-packed
    for (int idx = tid; idx < WDUP_ULL; idx += 256) {
        int c = idx & 511;
        int gate = (idx >> 9) & 3;
        int cl = idx >> 11;
        float v = __ldg(whh + ((size_t)gate * HH + (j0 + cl)) * HH + c);
        wdup[(cl * 4 + gate) * 512 + c] = dup2(v);
    }

    const ull* wp0 = wdup + (cell * 4 + g0) * 512;
    const ull* wp1 = wdup + (cell * 4 + g1) * 512;
    const ull* hrow = hp + b2 * HROW_PAD;

    float cst0 = 0.0f, cst1 = 0.0f;

    for (int step = 0; step < LL; step++) {
        int t = dir ? (LL - 1 - step) : step;
        const ull* hread = g_h2[step & 1][dir];
        ull* hwrite = g_h2[(step & 1) ^ 1][dir];

        // stage h into padded smem
        for (int i = tid; i < 16 * 512; i += 256) {
            int rb = i >> 9, rc = i & 511;
            hp[rb * HROW_PAD + rc] = hread[i];
        }
        __syncthreads();

        const float* gxp = g_gx + ((size_t)dir * LL + t) * (size_t)(GG * BB);
        ull a0 = *(const ull*)(gxp + ((size_t)g0 * HH + jglob) * 32 + 2 * b2);
        ull a1 = *(const ull*)(gxp + ((size_t)g1 * HH + jglob) * 32 + 2 * b2);

#pragma unroll 4
        for (int c = 0; c < HH; c += 4) {
            ull h0 = hrow[c], h1 = hrow[c + 1], h2 = hrow[c + 2], h3 = hrow[c + 3];
            ulonglong2 wa = *(const ulonglong2*)(wp0 + c);
            ulonglong2 wb = *(const ulonglong2*)(wp0 + c + 2);
            ulonglong2 wc = *(const ulonglong2*)(wp1 + c);
            ulonglong2 wd = *(const ulonglong2*)(wp1 + c + 2);
            ffma2(a0, wa.x, h0); ffma2(a1, wc.x, h0);
            ffma2(a0, wa.y, h1); ffma2(a1, wc.y, h1);
            ffma2(a0, wb.x, h2); ffma2(a1, wd.x, h2);
            ffma2(a0, wb.y, h3); ffma2(a1, wd.y, h3);
        }

        ull o0 = __shfl_xor_sync(0xffffffffu, a0, 16);
        ull o1 = __shfl_xor_sync(0xffffffffu, a1, 16);
        ull ui, uf, ug, uo;
        if (gpair == 0) { ui = a0; uf = a1; ug = o0; uo = o1; }
        else            { ui = o0; uf = o1; ug = a0; uo = a1; }

        float i0 = lo2(ui), i1 = hi2(ui);
        float f0 = lo2(uf), f1 = hi2(uf);
        float gg0 = lo2(ug), gg1 = hi2(ug);
        float oo0 = lo2(uo), oo1 = hi2(uo);

        float si0 = 1.0f / (1.0f + __expf(-i0));
        float sf0 = 1.0f / (1.0f + __expf(-f0));
        float so0 = 1.0f / (1.0f + __expf(-oo0));
        float tg0 = tanhf(gg0);
        cst0 = fmaf(sf0, cst0, si0 * tg0);
        float hn0 = so0 * tanhf(cst0);

        float si1 = 1.0f / (1.0f + __expf(-i1));
        float sf1 = 1.0f / (1.0f + __expf(-f1));
        float so1 = 1.0f / (1.0f + __expf(-oo1));
        float tg1 = tanhf(gg1);
        cst1 = fmaf(sf1, cst1, si1 * tg1);
        float hn1 = so1 * tanhf(cst1);

        if (gpair == 0) {
            unsigned u0 = __float_as_uint(hn0), u1 = __float_as_uint(hn1);
            hwrite[b2 * 512 + jglob] = ((ull)u1 << 32) | (ull)u0;
            *(float2*)(g_hall2 + ((size_t)t * 1024 + dir * HH + jglob) * 32 + 2 * b2)
                = make_float2(hn0, hn1);
        }

        grid_sync(128);
    }
}

// ---------------- head 2: out = z @ w2^T + b2 ------------------------------
__global__ void __launch_bounds__(256) head2_kernel(const float* __restrict__ w2,
                                                    const float* __restrict__ b2,
                                                    float* __restrict__ out) {
    int warp = (blockIdx.x * blockDim.x + threadIdx.x) >> 5;
    int lane = threadIdx.x & 31;
    if (warp >= NT) return;
    const float* z = g_z + (size_t)warp * 512;
    float zr[16];
#pragma unroll
    for (int i = 0; i < 16; i++) zr[i] = z[lane + 32 * i];
    int l = warp >> 5, b = warp & 31;
    float* op = out + ((size_t)b * LL + l) * NCLS;
    for (int cls = 0; cls < NCLS; cls++) {
        const float* wr = w2 + cls * 512;
        float s = 0.0f;
#pragma unroll
        for (int i = 0; i < 16; i++) s = fmaf(zr[i], wr[lane + 32 * i], s);
#pragma unroll
        for (int o = 16; o > 0; o >>= 1) s += __shfl_xor_sync(0xffffffffu, s, o);
        if (lane == 0) op[cls] = s + b2[cls];
    }
}

// ---------------- launcher -------------------------------------------------
extern "C" void kernel_launch(void* const* d_in, const int* in_sizes, int n_in,
                              void* d_out, int out_size) {
    (void)in_sizes; (void)n_in; (void)out_size;
    const int*   word_ids = (const int*)d_in[0];
    const int*   char_ids = (const int*)d_in[1];
    const float* char_emb = (const float*)d_in[3];
    const float* word_emb = (const float*)d_in[4];
    const float* conv_w   = (const float*)d_in[5];
    const float* conv_b   = (const float*)d_in[6];
    const float* w_ih_f   = (const float*)d_in[7];
    const float* w_hh_f   = (const float*)d_in[8];
    const float* b_f      = (const float*)d_in[9];
    const float* w_ih_b   = (const float*)d_in[10];
    const float* w_hh_b   = (const float*)d_in[11];
    const float* b_b      = (const float*)d_in[12];
    const float* w1       = (const float*)d_in[13];
    const float* b1       = (const float*)d_in[14];
    const float* w2       = (const float*)d_in[15];
    const float* b2       = (const float*)d_in[16];
    float* out = (float*)d_out;

    float *pX, *pGx, *pHall, *pZ;
    cudaGetSymbolAddress((void**)&pX,    g_X);
    cudaGetSymbolAddress((void**)&pGx,   g_gx);
    cudaGetSymbolAddress((void**)&pHall, g_hall2);
    cudaGetSymbolAddress((void**)&pZ,    g_z);

    cudaFuncSetAttribute(cnn_kernel,  cudaFuncAttributeMaxDynamicSharedMemorySize, CNN_SMEM);
    cudaFuncSetAttribute(lstm_kernel, cudaFuncAttributeMaxDynamicSharedMemorySize, LSTM_SMEM);

    init_kernel<<<80, 256>>>();
    embed_kernel<<<(NT * 64) / 256, 256>>>(word_ids, word_emb);
    cnn_kernel<<<512, 256, CNN_SMEM>>>(char_ids, char_emb, conv_w, conv_b);

    sgemm2_kernel<0, 0><<<dim3(GG / 128, NT / 128), 256>>>(pX, w_ih_f, b_f, pGx,
                                                           NT, GG, EMB);
    sgemm2_kernel<0, 0><<<dim3(GG / 128, NT / 128), 256>>>(pX, w_ih_b, b_b,
                                                           pGx + (size_t)LL * GG * BB,
                                                           NT, GG, EMB);

    lstm_kernel<<<128, 256, LSTM_SMEM>>>(w_hh_f, w_hh_b);

    sgemm2_kernel<1, 1><<<dim3(512 / 128, NT / 128), 256>>>(pHall, w1, b1, pZ,
                                                            NT, 512, 1024);
    head2_kernel<<<(NT * 32) / 256, 256>>>(w2, b2, out);
}

// round 6
// speedup vs baseline: 1.7649x; 1.4562x over previous
#include <cuda_runtime.h>
#include <math.h>

typedef unsigned long long ull;

#define BB 32
#define LL 128
#define WW 16
#define CEMB 64
#define NF 128
#define WEMB 256
#define EMB 384
#define HH 512
#define GG 2048
#define NT 4096
#define NCLS 17

#define CNN_SMEM ((128*193 + 8*16*64) * 4)

// LSTM smem: h only, permuted layout, 32 rows of 516 floats
#define HROW 516
#define LSTM_SMEM (32 * HROW * 4)

// ---------------- scratch (device globals: no allocation allowed) ----------
__device__ float g_X[NT * EMB];                       // [token=t*32+b][384]
__device__ float g_gx[(size_t)2 * LL * GG * BB];      // [dir][t][gate*512+cell][b]
__device__ float g_h2[2][2][512 * 32];                // ping-pong [buf][dir][cell][b]
__device__ float g_hall2[(size_t)LL * 1024 * BB];     // [t][dir*512+cell][b]
__device__ float g_z[(size_t)NT * 512];               // [token][512]
__device__ unsigned g_count;
__device__ unsigned g_gen;

// ---------------- helpers --------------------------------------------------
__device__ __forceinline__ void ffma2(ull& d, ull a, ull b) {
    asm("fma.rn.f32x2 %0, %1, %2, %0;" : "+l"(d) : "l"(a), "l"(b));
}
__device__ __forceinline__ ull mul2(ull a, ull b) {
    ull r; asm("mul.rn.f32x2 %0, %1, %2;" : "=l"(r) : "l"(a), "l"(b)); return r;
}
__device__ __forceinline__ ull add2(ull a, ull b) {
    ull r; asm("add.rn.f32x2 %0, %1, %2;" : "=l"(r) : "l"(a), "l"(b)); return r;
}
__device__ __forceinline__ ull dup2(float v) {
    unsigned u = __float_as_uint(v);
    return ((ull)u << 32) | (ull)u;
}
__device__ __forceinline__ ull pack2(float a, float b) {
    return ((ull)__float_as_uint(b) << 32) | (ull)__float_as_uint(a);
}
__device__ __forceinline__ float lo2(ull x) { return __uint_as_float((unsigned)x); }
__device__ __forceinline__ float hi2(ull x) { return __uint_as_float((unsigned)(x >> 32)); }

__device__ __forceinline__ ull shflx2(ull v, int m) {
    unsigned lo = (unsigned)v, hi = (unsigned)(v >> 32);
    lo = __shfl_xor_sync(0xffffffffu, lo, m);
    hi = __shfl_xor_sync(0xffffffffu, hi, m);
    return ((ull)hi << 32) | (ull)lo;
}
__device__ __forceinline__ ull shfli2(ull v, int src) {
    unsigned lo = (unsigned)v, hi = (unsigned)(v >> 32);
    lo = __shfl_sync(0xffffffffu, lo, src);
    hi = __shfl_sync(0xffffffffu, hi, src);
    return ((ull)hi << 32) | (ull)lo;
}

// ---------------- DIY grid barrier (all 128 blocks resident) ---------------
__device__ __forceinline__ void grid_sync(unsigned nb) {
    __threadfence();
    __syncthreads();
    if (threadIdx.x == 0) {
        volatile unsigned* vg = &g_gen;
        unsigned gen = *vg;
        unsigned arr = atomicAdd(&g_count, 1u);
        if (arr == nb - 1u) {
            atomicExch(&g_count, 0u);
            __threadfence();
            atomicExch((unsigned*)&g_gen, gen + 1u);
        } else {
            while (*vg == gen) { __nanosleep(32); }
        }
    }
    __syncthreads();
}

// ---------------- init: zero h ping buffer + barrier state -----------------
__global__ void init_kernel() {
    int i = blockIdx.x * blockDim.x + threadIdx.x;
    if (i == 0) { g_count = 0u; g_gen = 0u; }
    if (i < 2 * 512 * 32) {
        g_h2[0][0][i] = 0.0f;   // buffer 0, both dirs (contiguous)
    }
}

// ---------------- word embedding gather -> X[:,128:384] --------------------
__global__ void embed_kernel(const int* __restrict__ wid,
                             const float* __restrict__ wemb) {
    int idx = blockIdx.x * blockDim.x + threadIdx.x;   // 4096*64
    int token = idx >> 6;
    int j = idx & 63;
    int l = token >> 5;
    int b = token & 31;
    int w = wid[b * LL + l];
    float4 v = *(const float4*)(wemb + (size_t)w * WEMB + j * 4);
    *(float4*)(g_X + (size_t)token * EMB + NF + j * 4) = v;
}

// ---------------- char CNN + relu + maxpool -> X[:,0:128] ------------------
__global__ void __launch_bounds__(256) cnn_kernel(const int* __restrict__ cid,
                                                  const float* __restrict__ cemb,
                                                  const float* __restrict__ cw,
                                                  const float* __restrict__ cb) {
    extern __shared__ float sm[];
    float* ws = sm;                 // [128][193] padded conv weights
    float* ce = sm + 128 * 193;     // [8][16][64] char embeddings
    int tid = threadIdx.x;

    for (int i = tid; i < NF * 192; i += 256)
        ws[(i / 192) * 193 + (i % 192)] = cw[i];

    int p0 = blockIdx.x * 8;        // p = b*128 + l
    for (int i = tid; i < 8 * WW * CEMB; i += 256) {
        int q = i >> 10;
        int w = (i >> 6) & 15;
        int c = i & 63;
        int id = cid[(p0 + q) * WW + w];
        ce[i] = cemb[id * CEMB + c];
    }
    __syncthreads();

    int f  = tid & 127;
    int qh = tid >> 7;
    float bias = cb[f];
    const float* wsf = ws + f * 193;

    for (int qq = 0; qq < 4; qq++) {
        int q = qh * 4 + qq;
        float acc[WW];
#pragma unroll
        for (int w = 0; w < WW; w++) acc[w] = bias;
        const float* cep = ce + q * (WW * CEMB);
        for (int c = 0; c < CEMB; c++) {
            float cr[WW];
#pragma unroll
            for (int w = 0; w < WW; w++) cr[w] = cep[w * CEMB + c];
            float k0 = wsf[c * 3 + 0];
            float k1 = wsf[c * 3 + 1];
            float k2 = wsf[c * 3 + 2];
#pragma unroll
            for (int w = 1; w < WW; w++)     acc[w] = fmaf(cr[w - 1], k0, acc[w]);
#pragma unroll
            for (int w = 0; w < WW; w++)     acc[w] = fmaf(cr[w],     k1, acc[w]);
#pragma unroll
            for (int w = 0; w < WW - 1; w++) acc[w] = fmaf(cr[w + 1], k2, acc[w]);
        }
        float m = 0.0f;
#pragma unroll
        for (int w = 0; w < WW; w++) m = fmaxf(m, acc[w]);
        int p = p0 + q;
        int bq = p >> 7;
        int lq = p & 127;
        g_X[(size_t)(lq * BB + bq) * EMB + f] = m;
    }
}

// ---------------- f32x2 128x128x8 register-tiled SGEMM ---------------------
template <int AMODE, int OMODE>
__global__ void __launch_bounds__(256, 2) sgemm2_kernel(const float* __restrict__ A,
                                                        const float* __restrict__ Bw,
                                                        const float* __restrict__ bias,
                                                        float* __restrict__ C,
                                                        int M, int N, int K) {
    __shared__ ull   Asd[8][130];   // dup-packed {a,a}
    __shared__ float Bs[8][128];
    int tid = threadIdx.x;
    int bm = blockIdx.y * 128;
    int bn = blockIdx.x * 128;
    int ty = tid >> 4, tx = tid & 15;

    int lrow = tid >> 1;
    int lcol = (tid & 1) * 4;
    const float* Bg = Bw + (size_t)(bn + lrow) * K + lcol;

    ull acc[8][4];
#pragma unroll
    for (int i = 0; i < 8; i++)
#pragma unroll
        for (int q = 0; q < 4; q++) acc[i][q] = 0ull;

    for (int k0 = 0; k0 < K; k0 += 8) {
        float4 b4 = *(const float4*)(Bg + k0);
        Bs[lcol + 0][lrow] = b4.x; Bs[lcol + 1][lrow] = b4.y;
        Bs[lcol + 2][lrow] = b4.z; Bs[lcol + 3][lrow] = b4.w;
        if (AMODE == 0) {
            const float* Ag = A + (size_t)(bm + lrow) * K + k0 + lcol;
            float4 a4 = *(const float4*)Ag;
            Asd[lcol + 0][lrow] = dup2(a4.x);
            Asd[lcol + 1][lrow] = dup2(a4.y);
            Asd[lcol + 2][lrow] = dup2(a4.z);
            Asd[lcol + 3][lrow] = dup2(a4.w);
        } else {
            int kk = tid >> 5;
            int mg = (tid & 31) * 4;
            int t  = (bm + mg) >> 5;
            int b0 = (bm + mg) & 31;
            float4 a4 = *(const float4*)(A + ((size_t)t * K + (k0 + kk)) * 32 + b0);
            Asd[kk][mg + 0] = dup2(a4.x);
            Asd[kk][mg + 1] = dup2(a4.y);
            Asd[kk][mg + 2] = dup2(a4.z);
            Asd[kk][mg + 3] = dup2(a4.w);
        }
        __syncthreads();
#pragma unroll
        for (int k = 0; k < 8; k++) {
            ull ar[8];
            ulonglong2 p0 = *(const ulonglong2*)&Asd[k][ty * 8 + 0];
            ulonglong2 p1 = *(const ulonglong2*)&Asd[k][ty * 8 + 2];
            ulonglong2 p2 = *(const ulonglong2*)&Asd[k][ty * 8 + 4];
            ulonglong2 p3 = *(const ulonglong2*)&Asd[k][ty * 8 + 6];
            ar[0] = p0.x; ar[1] = p0.y; ar[2] = p1.x; ar[3] = p1.y;
            ar[4] = p2.x; ar[5] = p2.y; ar[6] = p3.x; ar[7] = p3.y;
            ull br[4];
#pragma unroll
            for (int q = 0; q < 4; q++)
                br[q] = *(const ull*)&Bs[k][2 * (q * 16 + tx)];
#pragma unroll
            for (int i = 0; i < 8; i++)
#pragma unroll
                for (int q = 0; q < 4; q++)
                    ffma2(acc[i][q], ar[i], br[q]);
        }
        __syncthreads();
    }

#pragma unroll
    for (int i = 0; i < 8; i++) {
        int m = bm + ty * 8 + i;
#pragma unroll
        for (int q = 0; q < 4; q++) {
            int n0 = bn + 2 * (q * 16 + tx);
            float2 bv = *(const float2*)(bias + n0);
            float v0 = lo2(acc[i][q]) + bv.x;
            float v1 = hi2(acc[i][q]) + bv.y;
            if (OMODE == 0) {
                int t = m >> 5, b = m & 31;
                C[((size_t)t * N + n0) * 32 + b]       = v0;
                C[((size_t)t * N + n0 + 1) * 32 + b]   = v1;
            } else {
                if (v0 < 0.0f) v0 = expm1f(v0);
                if (v1 < 0.0f) v1 = expm1f(v1);
                *(float2*)(C + (size_t)m * N + n0) = make_float2(v0, v1);
            }
        }
    }
}

// ---------------- persistent BiLSTM: register-resident weights -------------
// 128 blocks (64/dir). warp = cell (8 cells/block). lane = 16-c chunk owner
// AND b-owner. Weights: 4 gates x 16 c, c-pair packed -> 32 ull regs.
// smem: h permuted [b][j*128 + lane*4 + w], c = lane*16 + j*4 + w, row=516.
__global__ void __launch_bounds__(256) lstm_kernel(const float* __restrict__ whh_f,
                                                   const float* __restrict__ whh_b) {
    extern __shared__ float hs[];   // [32][516]
    int tid = threadIdx.x;
    int dir = blockIdx.x >> 6;
    int blk = blockIdx.x & 63;
    int warp = tid >> 5;
    int lane = tid & 31;
    int cellg = blk * 8 + warp;     // global cell 0..511 within dir
    const float* whh = dir ? whh_b : whh_f;

    // ---- load weights into registers: w[g*8 + j*2 + p] = {W[c], W[c+1]},
    //      c = lane*16 + j*4 + 2p
    ull wr[32];
#pragma unroll
    for (int g = 0; g < 4; g++) {
        const float* row = whh + ((size_t)g * HH + cellg) * HH + lane * 16;
#pragma unroll
        for (int j = 0; j < 4; j++)
#pragma unroll
            for (int p = 0; p < 2; p++) {
                float w0 = __ldg(row + j * 4 + 2 * p);
                float w1 = __ldg(row + j * 4 + 2 * p + 1);
                wr[g * 8 + j * 2 + p] = pack2(w0, w1);
            }
    }

    float cst = 0.0f;

    for (int step = 0; step < LL; step++) {
        int t = dir ? (LL - 1 - step) : step;
        const float* hread = g_h2[step & 1][dir];
        float* hwrite = g_h2[(step & 1) ^ 1][dir];

        // ---- stage h into permuted smem: thread (group=warp, b=lane)
        {
            int b = lane;
            int group = warp;
#pragma unroll
            for (int pass = 0; pass < 16; pass++) {
                int c0 = group * 64 + pass * 4;
                float v0 = hread[(c0 + 0) * 32 + b];
                float v1 = hread[(c0 + 1) * 32 + b];
                float v2 = hread[(c0 + 2) * 32 + b];
                float v3 = hread[(c0 + 3) * 32 + b];
                int j = (c0 >> 2) & 3;
                int l = c0 >> 4;
                *(float4*)(hs + b * HROW + j * 128 + l * 4) =
                    make_float4(v0, v1, v2, v3);
            }
        }
        __syncthreads();

        // ---- gx for this (cell, lane-as-b)
        const float* gxp = g_gx + ((size_t)dir * LL + t) * (size_t)(GG * BB);
        float gxi = gxp[(0 * HH + cellg) * 32 + lane];
        float gxf = gxp[(1 * HH + cellg) * 32 + lane];
        float gxg = gxp[(2 * HH + cellg) * 32 + lane];
        float gxo = gxp[(3 * HH + cellg) * 32 + lane];

        ull Ui = 0, Uf = 0, Ug = 0, Uo = 0;

#pragma unroll 2
        for (int b = 0; b < 32; b++) {
            const float* rowp = hs + b * HROW + lane * 4;
            ulonglong2 h0 = *(const ulonglong2*)(rowp + 0 * 128);
            ulonglong2 h1 = *(const ulonglong2*)(rowp + 1 * 128);
            ulonglong2 h2 = *(const ulonglong2*)(rowp + 2 * 128);
            ulonglong2 h3 = *(const ulonglong2*)(rowp + 3 * 128);

            ull a0 = mul2(wr[0], h0.x);
            ull a1 = mul2(wr[8], h0.x);
            ull a2 = mul2(wr[16], h0.x);
            ull a3 = mul2(wr[24], h0.x);
            ffma2(a0, wr[1], h0.y); ffma2(a1, wr[9], h0.y);
            ffma2(a2, wr[17], h0.y); ffma2(a3, wr[25], h0.y);
            ffma2(a0, wr[2], h1.x); ffma2(a1, wr[10], h1.x);
            ffma2(a2, wr[18], h1.x); ffma2(a3, wr[26], h1.x);
            ffma2(a0, wr[3], h1.y); ffma2(a1, wr[11], h1.y);
            ffma2(a2, wr[19], h1.y); ffma2(a3, wr[27], h1.y);
            ffma2(a0, wr[4], h2.x); ffma2(a1, wr[12], h2.x);
            ffma2(a2, wr[20], h2.x); ffma2(a3, wr[28], h2.x);
            ffma2(a0, wr[5], h2.y); ffma2(a1, wr[13], h2.y);
            ffma2(a2, wr[21], h2.y); ffma2(a3, wr[29], h2.y);
            ffma2(a0, wr[6], h3.x); ffma2(a1, wr[14], h3.x);
            ffma2(a2, wr[22], h3.x); ffma2(a3, wr[30], h3.x);
            ffma2(a0, wr[7], h3.y); ffma2(a1, wr[15], h3.y);
            ffma2(a2, wr[23], h3.y); ffma2(a3, wr[31], h3.y);

            // fold g0/g1 across xor16
            ull u  = (lane & 16) ? a0 : a1;
            ull v  = (lane & 16) ? a1 : a0;
            ull P01 = add2(v, shflx2(u, 16));
            // fold g2/g3 across xor16
            ull u2 = (lane & 16) ? a2 : a3;
            ull v2 = (lane & 16) ? a3 : a2;
            ull P23 = add2(v2, shflx2(u2, 16));
            // fold P01/P23 across xor8
            ull u3 = (lane & 8) ? P01 : P23;
            ull v3 = (lane & 8) ? P23 : P01;
            ull Q = add2(v3, shflx2(u3, 8));
            // plain reduce over bits 2..0
            Q = add2(Q, shflx2(Q, 4));
            Q = add2(Q, shflx2(Q, 2));
            Q = add2(Q, shflx2(Q, 1));
            // gate at lane bits (4,3): 00->i, 10->f, 01->g, 11->o
            int s = b & 7;
            ull ti = shfli2(Q, s);
            ull tf = shfli2(Q, s | 16);
            ull tg = shfli2(Q, s | 8);
            ull to = shfli2(Q, s | 24);
            bool own = (lane == b);
            Ui = own ? ti : Ui;
            Uf = own ? tf : Uf;
            Ug = own ? tg : Ug;
            Uo = own ? to : Uo;
        }

        // ---- activations for b = lane
        float xi = lo2(Ui) + hi2(Ui) + gxi;
        float xf = lo2(Uf) + hi2(Uf) + gxf;
        float xg = lo2(Ug) + hi2(Ug) + gxg;
        float xo = lo2(Uo) + hi2(Uo) + gxo;

        float si = 1.0f / (1.0f + __expf(-xi));
        float sf = 1.0f / (1.0f + __expf(-xf));
        float so = 1.0f / (1.0f + __expf(-xo));
        float tg2 = tanhf(xg);
        cst = fmaf(sf, cst, si * tg2);
        float hn = so * tanhf(cst);

        hwrite[cellg * 32 + lane] = hn;
        g_hall2[((size_t)t * 1024 + dir * HH + cellg) * 32 + lane] = hn;

        grid_sync(128);
    }
}

// ---------------- head 2: out = z @ w2^T + b2 ------------------------------
__global__ void __launch_bounds__(256) head2_kernel(const float* __restrict__ w2,
                                                    const float* __restrict__ b2,
                                                    float* __restrict__ out) {
    int warp = (blockIdx.x * blockDim.x + threadIdx.x) >> 5;
    int lane = threadIdx.x & 31;
    if (warp >= NT) return;
    const float* z = g_z + (size_t)warp * 512;
    float zr[16];
#pragma unroll
    for (int i = 0; i < 16; i++) zr[i] = z[lane + 32 * i];
    int l = warp >> 5, b = warp & 31;
    float* op = out + ((size_t)b * LL + l) * NCLS;
    for (int cls = 0; cls < NCLS; cls++) {
        const float* wr = w2 + cls * 512;
        float s = 0.0f;
#pragma unroll
        for (int i = 0; i < 16; i++) s = fmaf(zr[i], wr[lane + 32 * i], s);
#pragma unroll
        for (int o = 16; o > 0; o >>= 1) s += __shfl_xor_sync(0xffffffffu, s, o);
        if (lane == 0) op[cls] = s + b2[cls];
    }
}

// ---------------- launcher -------------------------------------------------
extern "C" void kernel_launch(void* const* d_in, const int* in_sizes, int n_in,
                              void* d_out, int out_size) {
    (void)in_sizes; (void)n_in; (void)out_size;
    const int*   word_ids = (const int*)d_in[0];
    const int*   char_ids = (const int*)d_in[1];
    const float* char_emb = (const float*)d_in[3];
    const float* word_emb = (const float*)d_in[4];
    const float* conv_w   = (const float*)d_in[5];
    const float* conv_b   = (const float*)d_in[6];
    const float* w_ih_f   = (const float*)d_in[7];
    const float* w_hh_f   = (const float*)d_in[8];
    const float* b_f      = (const float*)d_in[9];
    const float* w_ih_b   = (const float*)d_in[10];
    const float* w_hh_b   = (const float*)d_in[11];
    const float* b_b      = (const float*)d_in[12];
    const float* w1       = (const float*)d_in[13];
    const float* b1       = (const float*)d_in[14];
    const float* w2       = (const float*)d_in[15];
    const float* b2       = (const float*)d_in[16];
    float* out = (float*)d_out;

    float *pX, *pGx, *pHall, *pZ;
    cudaGetSymbolAddress((void**)&pX,    g_X);
    cudaGetSymbolAddress((void**)&pGx,   g_gx);
    cudaGetSymbolAddress((void**)&pHall, g_hall2);
    cudaGetSymbolAddress((void**)&pZ,    g_z);

    cudaFuncSetAttribute(cnn_kernel,  cudaFuncAttributeMaxDynamicSharedMemorySize, CNN_SMEM);
    cudaFuncSetAttribute(lstm_kernel, cudaFuncAttributeMaxDynamicSharedMemorySize, LSTM_SMEM);

    init_kernel<<<128, 256>>>();
    embed_kernel<<<(NT * 64) / 256, 256>>>(word_ids, word_emb);
    cnn_kernel<<<512, 256, CNN_SMEM>>>(char_ids, char_emb, conv_w, conv_b);

    sgemm2_kernel<0, 0><<<dim3(GG / 128, NT / 128), 256>>>(pX, w_ih_f, b_f, pGx,
                                                           NT, GG, EMB);
    sgemm2_kernel<0, 0><<<dim3(GG / 128, NT / 128), 256>>>(pX, w_ih_b, b_b,
                                                           pGx + (size_t)LL * GG * BB,
                                                           NT, GG, EMB);

    lstm_kernel<<<128, 256, LSTM_SMEM>>>(w_hh_f, w_hh_b);

    sgemm2_kernel<1, 1><<<dim3(512 / 128, NT / 128), 256>>>(pHall, w1, b1, pZ,
                                                            NT, 512, 1024);
    head2_kernel<<<(NT * 32) / 256, 256>>>(w2, b2, out);
}

// round 7
// speedup vs baseline: 2.0378x; 1.1546x over previous
#include <cuda_runtime.h>
#include <math.h>

typedef unsigned long long ull;

#define BB 32
#define LL 128
#define WW 16
#define CEMB 64
#define NF 128
#define WEMB 256
#define EMB 384
#define HH 512
#define GG 2048
#define NT 4096
#define NCLS 17

#define CNN_SMEM ((128*193 + 8*16*64) * 4)

// LSTM smem: h permuted [32][516] + reduction slab [8 warps][4 gates][33]
#define HROW 516
#define REDW 132
#define LSTM_SMEM ((32 * HROW + 8 * REDW) * 4)

// ---------------- scratch (device globals: no allocation allowed) ----------
__device__ float g_X[NT * EMB];                       // [token=t*32+b][384]
__device__ float g_gx[(size_t)2 * LL * GG * BB];      // [dir][t][gate*512+cell][b]
__device__ float g_h2[2][2][512 * 32];                // ping-pong [buf][dir][cell][b]
__device__ float g_hall2[(size_t)LL * 1024 * BB];     // [t][dir*512+cell][b]
__device__ float g_z[(size_t)NT * 512];               // [token][512]
__device__ unsigned g_grp[16];
__device__ unsigned g_root;
__device__ volatile unsigned g_gen;

// ---------------- helpers --------------------------------------------------
__device__ __forceinline__ void ffma2(ull& d, ull a, ull b) {
    asm("fma.rn.f32x2 %0, %1, %2, %0;" : "+l"(d) : "l"(a), "l"(b));
}
__device__ __forceinline__ ull mul2(ull a, ull b) {
    ull r; asm("mul.rn.f32x2 %0, %1, %2;" : "=l"(r) : "l"(a), "l"(b)); return r;
}
__device__ __forceinline__ ull dup2(float v) {
    unsigned u = __float_as_uint(v);
    return ((ull)u << 32) | (ull)u;
}
__device__ __forceinline__ ull pack2(float a, float b) {
    return ((ull)__float_as_uint(b) << 32) | (ull)__float_as_uint(a);
}
__device__ __forceinline__ float lo2(ull x) { return __uint_as_float((unsigned)x); }
__device__ __forceinline__ float hi2(ull x) { return __uint_as_float((unsigned)(x >> 32)); }

// fold: lanes with bit==0 end holding pair-sum of x, bit==1 pair-sum of y
__device__ __forceinline__ float foldf(float x, float y, int mask, bool bit) {
    float send = bit ? x : y;
    float keep = bit ? y : x;
    return keep + __shfl_xor_sync(0xffffffffu, send, mask);
}

// ---------------- two-level tree grid barrier (128 blocks) -----------------
__device__ __forceinline__ void grid_sync_tree(int bid) {
    __threadfence();
    __syncthreads();
    if (threadIdx.x == 0) {
        unsigned gen = g_gen;
        unsigned ga = atomicAdd(&g_grp[bid >> 3], 1u);
        if (ga == 7u) {
            unsigned ra = atomicAdd(&g_root, 1u);
            if (ra == 15u) {
#pragma unroll
                for (int i = 0; i < 16; i++) g_grp[i] = 0u;
                g_root = 0u;
                __threadfence();
                g_gen = gen + 1u;
            } else {
                while (g_gen == gen) __nanosleep(32);
            }
        } else {
            while (g_gen == gen) __nanosleep(32);
        }
    }
    __syncthreads();
}

// ---------------- init: zero h ping buffer + barrier state -----------------
__global__ void init_kernel() {
    int i = blockIdx.x * blockDim.x + threadIdx.x;
    if (i == 0) { g_root = 0u; g_gen = 0u; }
    if (i < 16) g_grp[i] = 0u;
    if (i < 2 * 512 * 32) {
        g_h2[0][0][i] = 0.0f;   // buffer 0, both dirs (contiguous)
    }
}

// ---------------- word embedding gather -> X[:,128:384] --------------------
__global__ void embed_kernel(const int* __restrict__ wid,
                             const float* __restrict__ wemb) {
    int idx = blockIdx.x * blockDim.x + threadIdx.x;   // 4096*64
    int token = idx >> 6;
    int j = idx & 63;
    int l = token >> 5;
    int b = token & 31;
    int w = wid[b * LL + l];
    float4 v = *(const float4*)(wemb + (size_t)w * WEMB + j * 4);
    *(float4*)(g_X + (size_t)token * EMB + NF + j * 4) = v;
}

// ---------------- char CNN + relu + maxpool -> X[:,0:128] ------------------
__global__ void __launch_bounds__(256) cnn_kernel(const int* __restrict__ cid,
                                                  const float* __restrict__ cemb,
                                                  const float* __restrict__ cw,
                                                  const float* __restrict__ cb) {
    extern __shared__ float sm[];
    float* ws = sm;                 // [128][193] padded conv weights
    float* ce = sm + 128 * 193;     // [8][16][64] char embeddings
    int tid = threadIdx.x;

    for (int i = tid; i < NF * 192; i += 256)
        ws[(i / 192) * 193 + (i % 192)] = cw[i];

    int p0 = blockIdx.x * 8;        // p = b*128 + l
    for (int i = tid; i < 8 * WW * CEMB; i += 256) {
        int q = i >> 10;
        int w = (i >> 6) & 15;
        int c = i & 63;
        int id = cid[(p0 + q) * WW + w];
        ce[i] = cemb[id * CEMB + c];
    }
    __syncthreads();

    int f  = tid & 127;
    int qh = tid >> 7;
    float bias = cb[f];
    const float* wsf = ws + f * 193;

    for (int qq = 0; qq < 4; qq++) {
        int q = qh * 4 + qq;
        float acc[WW];
#pragma unroll
        for (int w = 0; w < WW; w++) acc[w] = bias;
        const float* cep = ce + q * (WW * CEMB);
        for (int c = 0; c < CEMB; c++) {
            float cr[WW];
#pragma unroll
            for (int w = 0; w < WW; w++) cr[w] = cep[w * CEMB + c];
            float k0 = wsf[c * 3 + 0];
            float k1 = wsf[c * 3 + 1];
            float k2 = wsf[c * 3 + 2];
#pragma unroll
            for (int w = 1; w < WW; w++)     acc[w] = fmaf(cr[w - 1], k0, acc[w]);
#pragma unroll
            for (int w = 0; w < WW; w++)     acc[w] = fmaf(cr[w],     k1, acc[w]);
#pragma unroll
            for (int w = 0; w < WW - 1; w++) acc[w] = fmaf(cr[w + 1], k2, acc[w]);
        }
        float m = 0.0f;
#pragma unroll
        for (int w = 0; w < WW; w++) m = fmaxf(m, acc[w]);
        int p = p0 + q;
        int bq = p >> 7;
        int lq = p & 127;
        g_X[(size_t)(lq * BB + bq) * EMB + f] = m;
    }
}

// ---------------- f32x2 128x128x8 register-tiled SGEMM ---------------------
template <int AMODE, int OMODE>
__global__ void __launch_bounds__(256, 2) sgemm2_kernel(const float* __restrict__ A,
                                                        const float* __restrict__ Bw,
                                                        const float* __restrict__ bias,
                                                        float* __restrict__ C,
                                                        int M, int N, int K) {
    __shared__ ull   Asd[8][130];   // dup-packed {a,a}
    __shared__ float Bs[8][128];
    int tid = threadIdx.x;
    int bm = blockIdx.y * 128;
    int bn = blockIdx.x * 128;
    int ty = tid >> 4, tx = tid & 15;

    int lrow = tid >> 1;
    int lcol = (tid & 1) * 4;
    const float* Bg = Bw + (size_t)(bn + lrow) * K + lcol;

    ull acc[8][4];
#pragma unroll
    for (int i = 0; i < 8; i++)
#pragma unroll
        for (int q = 0; q < 4; q++) acc[i][q] = 0ull;

    for (int k0 = 0; k0 < K; k0 += 8) {
        float4 b4 = *(const float4*)(Bg + k0);
        Bs[lcol + 0][lrow] = b4.x; Bs[lcol + 1][lrow] = b4.y;
        Bs[lcol + 2][lrow] = b4.z; Bs[lcol + 3][lrow] = b4.w;
        if (AMODE == 0) {
            const float* Ag = A + (size_t)(bm + lrow) * K + k0 + lcol;
            float4 a4 = *(const float4*)Ag;
            Asd[lcol + 0][lrow] = dup2(a4.x);
            Asd[lcol + 1][lrow] = dup2(a4.y);
            Asd[lcol + 2][lrow] = dup2(a4.z);
            Asd[lcol + 3][lrow] = dup2(a4.w);
        } else {
            int kk = tid >> 5;
            int mg = (tid & 31) * 4;
            int t  = (bm + mg) >> 5;
            int b0 = (bm + mg) & 31;
            float4 a4 = *(const float4*)(A + ((size_t)t * K + (k0 + kk)) * 32 + b0);
            Asd[kk][mg + 0] = dup2(a4.x);
            Asd[kk][mg + 1] = dup2(a4.y);
            Asd[kk][mg + 2] = dup2(a4.z);
            Asd[kk][mg + 3] = dup2(a4.w);
        }
        __syncthreads();
#pragma unroll
        for (int k = 0; k < 8; k++) {
            ull ar[8];
            ulonglong2 p0 = *(const ulonglong2*)&Asd[k][ty * 8 + 0];
            ulonglong2 p1 = *(const ulonglong2*)&Asd[k][ty * 8 + 2];
            ulonglong2 p2 = *(const ulonglong2*)&Asd[k][ty * 8 + 4];
            ulonglong2 p3 = *(const ulonglong2*)&Asd[k][ty * 8 + 6];
            ar[0] = p0.x; ar[1] = p0.y; ar[2] = p1.x; ar[3] = p1.y;
            ar[4] = p2.x; ar[5] = p2.y; ar[6] = p3.x; ar[7] = p3.y;
            ull br[4];
#pragma unroll
            for (int q = 0; q < 4; q++)
                br[q] = *(const ull*)&Bs[k][2 * (q * 16 + tx)];
#pragma unroll
            for (int i = 0; i < 8; i++)
#pragma unroll
                for (int q = 0; q < 4; q++)
                    ffma2(acc[i][q], ar[i], br[q]);
        }
        __syncthreads();
    }

#pragma unroll
    for (int i = 0; i < 8; i++) {
        int m = bm + ty * 8 + i;
#pragma unroll
        for (int q = 0; q < 4; q++) {
            int n0 = bn + 2 * (q * 16 + tx);
            float2 bv = *(const float2*)(bias + n0);
            float v0 = lo2(acc[i][q]) + bv.x;
            float v1 = hi2(acc[i][q]) + bv.y;
            if (OMODE == 0) {
                int t = m >> 5, b = m & 31;
                C[((size_t)t * N + n0) * 32 + b]       = v0;
                C[((size_t)t * N + n0 + 1) * 32 + b]   = v1;
            } else {
                if (v0 < 0.0f) v0 = expm1f(v0);
                if (v1 < 0.0f) v1 = expm1f(v1);
                *(float2*)(C + (size_t)m * N + n0) = make_float2(v0, v1);
            }
        }
    }
}

// ---------------- persistent BiLSTM: reg weights + batch-4 fold ------------
// 128 blocks (64/dir). warp = cell. lane = 16-c chunk owner AND b-owner.
// Per step: 8 batches of 4 b; per batch 128 ffma2 + 16-SHFL fold tree that
// lands (gate,b_local) on lane bits {4,3},{1,2}; results via padded smem.
__global__ void __launch_bounds__(256) lstm_kernel(const float* __restrict__ whh_f,
                                                   const float* __restrict__ whh_b) {
    extern __shared__ float hs[];   // [32][516] then red [8][4][33]
    float* red = hs + 32 * HROW;
    int tid = threadIdx.x;
    int dir = blockIdx.x >> 6;
    int blk = blockIdx.x & 63;
    int warp = tid >> 5;
    int lane = tid & 31;
    int cellg = blk * 8 + warp;     // global cell 0..511 within dir
    const float* whh = dir ? whh_b : whh_f;

    // writer lane's (gate, b_local) per fold-tree landing pattern
    int w_gate = ((lane >> 4) & 1) + 2 * ((lane >> 3) & 1);   // 00->i 10->f 01->g 11->o
    int w_bl   = 2 * ((lane >> 1) & 1) + ((lane >> 2) & 1);
    bool w_own = (lane & 1) == 0;
    float* w_slot = red + warp * REDW + w_gate * 33;

    // ---- load weights into registers: wr[g*8 + j*2 + p] = {W[c], W[c+1]},
    //      c = lane*16 + j*4 + 2p
    ull wr[32];
#pragma unroll
    for (int g = 0; g < 4; g++) {
        const float* row = whh + ((size_t)g * HH + cellg) * HH + lane * 16;
#pragma unroll
        for (int j = 0; j < 4; j++)
#pragma unroll
            for (int p = 0; p < 2; p++) {
                float w0 = __ldg(row + j * 4 + 2 * p);
                float w1 = __ldg(row + j * 4 + 2 * p + 1);
                wr[g * 8 + j * 2 + p] = pack2(w0, w1);
            }
    }

    float cst = 0.0f;

    for (int step = 0; step < LL; step++) {
        int t = dir ? (LL - 1 - step) : step;
        const float* hread = g_h2[step & 1][dir];
        float* hwrite = g_h2[(step & 1) ^ 1][dir];

        // ---- stage h into permuted smem: thread (group=warp, b=lane)
        {
            int b = lane;
            int group = warp;
#pragma unroll
            for (int pass = 0; pass < 16; pass++) {
                int c0 = group * 64 + pass * 4;
                float v0 = hread[(c0 + 0) * 32 + b];
                float v1 = hread[(c0 + 1) * 32 + b];
                float v2 = hread[(c0 + 2) * 32 + b];
                float v3 = hread[(c0 + 3) * 32 + b];
                int j = (c0 >> 2) & 3;
                int l = c0 >> 4;
                *(float4*)(hs + b * HROW + j * 128 + l * 4) =
                    make_float4(v0, v1, v2, v3);
            }
        }
        __syncthreads();

        // ---- gx for this (cell, lane-as-b)
        const float* gxp = g_gx + ((size_t)dir * LL + t) * (size_t)(GG * BB);
        float gxi = gxp[(0 * HH + cellg) * 32 + lane];
        float gxf = gxp[(1 * HH + cellg) * 32 + lane];
        float gxg = gxp[(2 * HH + cellg) * 32 + lane];
        float gxo = gxp[(3 * HH + cellg) * 32 + lane];

#pragma unroll
        for (int batch = 0; batch < 8; batch++) {
            float s[4][4];
#pragma unroll
            for (int bl = 0; bl < 4; bl++) {
                const float* rowp = hs + (batch * 4 + bl) * HROW + lane * 4;
                ulonglong2 h0 = *(const ulonglong2*)(rowp + 0);
                ulonglong2 h1 = *(const ulonglong2*)(rowp + 128);
                ulonglong2 h2 = *(const ulonglong2*)(rowp + 256);
                ulonglong2 h3 = *(const ulonglong2*)(rowp + 384);
                ull a0 = mul2(wr[0],  h0.x);
                ull a1 = mul2(wr[8],  h0.x);
                ull a2 = mul2(wr[16], h0.x);
                ull a3 = mul2(wr[24], h0.x);
                ffma2(a0, wr[1],  h0.y); ffma2(a1, wr[9],  h0.y);
                ffma2(a2, wr[17], h0.y); ffma2(a3, wr[25], h0.y);
                ffma2(a0, wr[2],  h1.x); ffma2(a1, wr[10], h1.x);
                ffma2(a2, wr[18], h1.x); ffma2(a3, wr[26], h1.x);
                ffma2(a0, wr[3],  h1.y); ffma2(a1, wr[11], h1.y);
                ffma2(a2, wr[19], h1.y); ffma2(a3, wr[27], h1.y);
                ffma2(a0, wr[4],  h2.x); ffma2(a1, wr[12], h2.x);
                ffma2(a2, wr[20], h2.x); ffma2(a3, wr[28], h2.x);
                ffma2(a0, wr[5],  h2.y); ffma2(a1, wr[13], h2.y);
                ffma2(a2, wr[21], h2.y); ffma2(a3, wr[29], h2.y);
                ffma2(a0, wr[6],  h3.x); ffma2(a1, wr[14], h3.x);
                ffma2(a2, wr[22], h3.x); ffma2(a3, wr[30], h3.x);
                ffma2(a0, wr[7],  h3.y); ffma2(a1, wr[15], h3.y);
                ffma2(a2, wr[23], h3.y); ffma2(a3, wr[31], h3.y);
                s[bl][0] = lo2(a0) + hi2(a0);
                s[bl][1] = lo2(a1) + hi2(a1);
                s[bl][2] = lo2(a2) + hi2(a2);
                s[bl][3] = lo2(a3) + hi2(a3);
            }
            // fold tree: gates onto bits {4,3}, b_local onto bits {1,2}
            bool b4 = (lane & 16) != 0;
            bool b3 = (lane & 8) != 0;
            bool b2f = (lane & 4) != 0;
            bool b1f = (lane & 2) != 0;
            float IF0 = foldf(s[0][0], s[0][1], 16, b4);
            float GO0 = foldf(s[0][2], s[0][3], 16, b4);
            float IF1 = foldf(s[1][0], s[1][1], 16, b4);
            float GO1 = foldf(s[1][2], s[1][3], 16, b4);
            float IF2 = foldf(s[2][0], s[2][1], 16, b4);
            float GO2 = foldf(s[2][2], s[2][3], 16, b4);
            float IF3 = foldf(s[3][0], s[3][1], 16, b4);
            float GO3 = foldf(s[3][2], s[3][3], 16, b4);
            float V0 = foldf(IF0, GO0, 8, b3);
            float V1 = foldf(IF1, GO1, 8, b3);
            float V2 = foldf(IF2, GO2, 8, b3);
            float V3 = foldf(IF3, GO3, 8, b3);
            float X = foldf(V0, V1, 4, b2f);
            float Y = foldf(V2, V3, 4, b2f);
            float Z = foldf(X, Y, 2, b1f);
            Z += __shfl_xor_sync(0xffffffffu, Z, 1);
            if (w_own) w_slot[batch * 4 + w_bl] = Z;
        }
        __syncwarp();

        // ---- activations for b = lane
        const float* rp = red + warp * REDW;
        float xi = rp[0 * 33 + lane] + gxi;
        float xf = rp[1 * 33 + lane] + gxf;
        float xg = rp[2 * 33 + lane] + gxg;
        float xo = rp[3 * 33 + lane] + gxo;

        float si = 1.0f / (1.0f + __expf(-xi));
        float sf = 1.0f / (1.0f + __expf(-xf));
        float so = 1.0f / (1.0f + __expf(-xo));
        float tg2 = tanhf(xg);
        cst = fmaf(sf, cst, si * tg2);
        float hn = so * tanhf(cst);

        hwrite[cellg * 32 + lane] = hn;
        g_hall2[((size_t)t * 1024 + dir * HH + cellg) * 32 + lane] = hn;

        grid_sync_tree(blockIdx.x);
    }
}

// ---------------- head 2: out = z @ w2^T + b2 ------------------------------
__global__ void __launch_bounds__(256) head2_kernel(const float* __restrict__ w2,
                                                    const float* __restrict__ b2,
                                                    float* __restrict__ out) {
    int warp = (blockIdx.x * blockDim.x + threadIdx.x) >> 5;
    int lane = threadIdx.x & 31;
    if (warp >= NT) return;
    const float* z = g_z + (size_t)warp * 512;
    float zr[16];
#pragma unroll
    for (int i = 0; i < 16; i++) zr[i] = z[lane + 32 * i];
    int l = warp >> 5, b = warp & 31;
    float* op = out + ((size_t)b * LL + l) * NCLS;
    for (int cls = 0; cls < NCLS; cls++) {
        const float* wr = w2 + cls * 512;
        float s = 0.0f;
#pragma unroll
        for (int i = 0; i < 16; i++) s = fmaf(zr[i], wr[lane + 32 * i], s);
#pragma unroll
        for (int o = 16; o > 0; o >>= 1) s += __shfl_xor_sync(0xffffffffu, s, o);
        if (lane == 0) op[cls] = s + b2[cls];
    }
}

// ---------------- launcher -------------------------------------------------
extern "C" void kernel_launch(void* const* d_in, const int* in_sizes, int n_in,
                              void* d_out, int out_size) {
    (void)in_sizes; (void)n_in; (void)out_size;
    const int*   word_ids = (const int*)d_in[0];
    const int*   char_ids = (const int*)d_in[1];
    const float* char_emb = (const float*)d_in[3];
    const float* word_emb = (const float*)d_in[4];
    const float* conv_w   = (const float*)d_in[5];
    const float* conv_b   = (const float*)d_in[6];
    const float* w_ih_f   = (const float*)d_in[7];
    const float* w_hh_f   = (const float*)d_in[8];
    const float* b_f      = (const float*)d_in[9];
    const float* w_ih_b   = (const float*)d_in[10];
    const float* w_hh_b   = (const float*)d_in[11];
    const float* b_b      = (const float*)d_in[12];
    const float* w1       = (const float*)d_in[13];
    const float* b1       = (const float*)d_in[14];
    const float* w2       = (const float*)d_in[15];
    const float* b2       = (const float*)d_in[16];
    float* out = (float*)d_out;

    float *pX, *pGx, *pHall, *pZ;
    cudaGetSymbolAddress((void**)&pX,    g_X);
    cudaGetSymbolAddress((void**)&pGx,   g_gx);
    cudaGetSymbolAddress((void**)&pHall, g_hall2);
    cudaGetSymbolAddress((void**)&pZ,    g_z);

    cudaFuncSetAttribute(cnn_kernel,  cudaFuncAttributeMaxDynamicSharedMemorySize, CNN_SMEM);
    cudaFuncSetAttribute(lstm_kernel, cudaFuncAttributeMaxDynamicSharedMemorySize, LSTM_SMEM);

    init_kernel<<<128, 256>>>();
    embed_kernel<<<(NT * 64) / 256, 256>>>(word_ids, word_emb);
    cnn_kernel<<<512, 256, CNN_SMEM>>>(char_ids, char_emb, conv_w, conv_b);

    sgemm2_kernel<0, 0><<<dim3(GG / 128, NT / 128), 256>>>(pX, w_ih_f, b_f, pGx,
                                                           NT, GG, EMB);
    sgemm2_kernel<0, 0><<<dim3(GG / 128, NT / 128), 256>>>(pX, w_ih_b, b_b,
                                                           pGx + (size_t)LL * GG * BB,
                                                           NT, GG, EMB);

    lstm_kernel<<<128, 256, LSTM_SMEM>>>(w_hh_f, w_hh_b);

    sgemm2_kernel<1, 1><<<dim3(512 / 128, NT / 128), 256>>>(pHall, w1, b1, pZ,
                                                            NT, 512, 1024);
    head2_kernel<<<(NT * 32) / 256, 256>>>(w2, b2, out);
}